// round 14
// baseline (speedup 1.0000x reference)
#include <cuda_runtime.h>
#include <cuda_bf16.h>
#include <math.h>
#include <stdint.h>

#define NT 8192
#define DM 1024
#define FF 4096
#define NE 8
#define TOTAL_ROWS (NT * 2)

// packed smem: per stage A[128 rows][9 uint4] + B[128 rows][9 uint4]
// row = 8 data uint4 (32 k as 16 hi/lo bf16x2 pairs) + 1 pad uint4
#define TROW 9
#define HDR4 128                       // 2048 B header (stok/sbias/swt)
#define TILE4 (128 * TROW)             // 1152 uint4
#define STAGE4 (2 * TILE4)             // A + B
#define SMEM_BYTES ((HDR4 + 2 * STAGE4) * 16)   // 75776 B

// ---------------- scratch (device globals; no runtime alloc) ----------------
__device__ int   g_cnt[NE];
__device__ int   g_off[NE];
__device__ int   g_tok[NE * NT];
__device__ float g_w  [NE * NT];
// padded by 128 rows so OOB-tile A loads in GEMM2 stay in-bounds
__device__ __align__(16) float g_h[(size_t)(TOTAL_ROWS + 128) * FF];
// fp32 transposed weights: W1t[e][n][k], W2t[e][n][k]
__device__ __align__(16) float g_w1t[(size_t)NE * FF * DM];
__device__ __align__(16) float g_w2t[(size_t)NE * DM * FF];

// ---------------- mma.sync (validated R7/R12) ----------------
__device__ __forceinline__ void mma_bf16(float (&d)[4], const uint32_t (&a)[4],
                                         uint32_t b0, uint32_t b1) {
    asm volatile("mma.sync.aligned.m16n8k16.row.col.f32.bf16.bf16.f32 "
        "{%0,%1,%2,%3}, {%4,%5,%6,%7}, {%8,%9}, {%0,%1,%2,%3};"
        : "+f"(d[0]), "+f"(d[1]), "+f"(d[2]), "+f"(d[3])
        : "r"(a[0]), "r"(a[1]), "r"(a[2]), "r"(a[3]), "r"(b0), "r"(b1));
}

// split two fp32 into packed bf16x2 hi and lo (identical arithmetic to R12)
__device__ __forceinline__ void split2(float v0, float v1, uint32_t& hi, uint32_t& lo) {
    __nv_bfloat162 h = __floats2bfloat162_rn(v0, v1);
    float r0 = v0 - __bfloat162float(h.x);
    float r1 = v1 - __bfloat162float(h.y);
    __nv_bfloat162 l = __floats2bfloat162_rn(r0, r1);
    hi = *reinterpret_cast<uint32_t*>(&h);
    lo = *reinterpret_cast<uint32_t*>(&l);
}

// pack 16 consecutive fp32 k-values (4 float4) into 4 interleaved uint4s:
// slot q = {hi(pair q), hi(pair q+4), lo(pair q), lo(pair q+4)}, pair p = k 2p,2p+1
__device__ __forceinline__ void pack16(uint4 (&dst)[4], const float4 (&v)[4]) {
    const float f[16] = {v[0].x, v[0].y, v[0].z, v[0].w,
                         v[1].x, v[1].y, v[1].z, v[1].w,
                         v[2].x, v[2].y, v[2].z, v[2].w,
                         v[3].x, v[3].y, v[3].z, v[3].w};
#pragma unroll
    for (int q = 0; q < 4; q++) {
        uint32_t h0, l0, h1, l1;
        split2(f[2 * q],     f[2 * q + 1], h0, l0);
        split2(f[2 * q + 8], f[2 * q + 9], h1, l1);
        dst[q].x = h0; dst[q].y = h1; dst[q].z = l0; dst[q].w = l1;
    }
}

// ---------------- zero counts + output ----------------
__global__ void zero_kernel(float* __restrict__ out) {
    int i = blockIdx.x * blockDim.x + threadIdx.x;
    if (i < NE) g_cnt[i] = 0;
    float4* o4 = reinterpret_cast<float4*>(out);
    if (i < NT * DM / 4) o4[i] = make_float4(0.f, 0.f, 0.f, 0.f);
}

// ---------------- gate (validated R1) ----------------
__global__ void gate_kernel(const float* __restrict__ x,
                            const float* __restrict__ Wg,
                            const float* __restrict__ bg) {
    int gtid = blockIdx.x * blockDim.x + threadIdx.x;
    int t = gtid >> 5, lane = gtid & 31;
    if (t >= NT) return;
    const float* xr = x + (size_t)t * DM;
    float acc[NE];
#pragma unroll
    for (int e = 0; e < NE; e++) acc[e] = 0.f;
    for (int k = lane; k < DM; k += 32) {
        float xv = xr[k];
        const float* wr = Wg + k * NE;
#pragma unroll
        for (int e = 0; e < NE; e++) acc[e] += xv * wr[e];
    }
#pragma unroll
    for (int s = 16; s > 0; s >>= 1)
#pragma unroll
        for (int e = 0; e < NE; e++) acc[e] += __shfl_xor_sync(0xffffffffu, acc[e], s);
    if (lane == 0) {
#pragma unroll
        for (int e = 0; e < NE; e++) acc[e] += bg[e];
        float mx = acc[0];
#pragma unroll
        for (int e = 1; e < NE; e++) mx = fmaxf(mx, acc[e]);
        float s = 0.f;
#pragma unroll
        for (int e = 0; e < NE; e++) { acc[e] = expf(acc[e] - mx); s += acc[e]; }
        float inv = 1.f / s;
#pragma unroll
        for (int e = 0; e < NE; e++) acc[e] *= inv;
        int i0 = 0;
#pragma unroll
        for (int e = 1; e < NE; e++) if (acc[e] > acc[i0]) i0 = e;
        int i1 = (i0 == 0) ? 1 : 0;
#pragma unroll
        for (int e = 0; e < NE; e++) if (e != i0 && acc[e] > acc[i1]) i1 = e;
        float s2 = acc[i0] + acc[i1] + 1e-9f;
        int p0 = atomicAdd(&g_cnt[i0], 1);
        g_tok[i0 * NT + p0] = t;  g_w[i0 * NT + p0] = acc[i0] / s2;
        int p1 = atomicAdd(&g_cnt[i1], 1);
        g_tok[i1 * NT + p1] = t;  g_w[i1 * NT + p1] = acc[i1] / s2;
    }
}

__global__ void offsets_kernel() {
    if (threadIdx.x == 0 && blockIdx.x == 0) {
        int s = 0;
#pragma unroll
        for (int e = 0; e < NE; e++) { g_off[e] = s; s += g_cnt[e]; }
    }
}

// ---------------- fp32 transpose: in [E][R][C] -> out [E][C][R] ----------------
__global__ void wtrans(const float* __restrict__ in, float* __restrict__ out,
                       int R, int C) {
    __shared__ float t[32][33];
    int e = blockIdx.z, c0 = blockIdx.x * 32, r0 = blockIdx.y * 32;
    const float* ie = in + (size_t)e * R * C;
    float* oe = out + (size_t)e * R * C;
    int tx = threadIdx.x & 31, ty = threadIdx.x >> 5;   // 32 x 8
#pragma unroll
    for (int i = 0; i < 4; i++)
        t[ty + i * 8][tx] = ie[(size_t)(r0 + ty + i * 8) * C + c0 + tx];
    __syncthreads();
#pragma unroll
    for (int i = 0; i < 4; i++)
        oe[(size_t)(c0 + ty + i * 8) * R + r0 + tx] = t[tx][ty + i * 8];
}

// ---- compute one k32 stage from packed tiles (R8-validated format, x2 k16) ----
__device__ __forceinline__ void compute_stage32(const uint4* __restrict__ A4,
                                                const uint4* __restrict__ B4,
                                                int wm, int wn, int lid,
                                                float (&acc)[2][8][4]) {
    const int qr = lid >> 2, q = lid & 3;
#pragma unroll
    for (int s = 0; s < 2; s++) {
        uint32_t ah[2][4], al[2][4];
#pragma unroll
        for (int mf = 0; mf < 2; mf++) {
            uint4 U1 = A4[(wm + mf * 16 + qr) * TROW + s * 4 + q];
            uint4 U2 = A4[(wm + mf * 16 + qr + 8) * TROW + s * 4 + q];
            ah[mf][0] = U1.x; ah[mf][1] = U2.x; ah[mf][2] = U1.y; ah[mf][3] = U2.y;
            al[mf][0] = U1.z; al[mf][1] = U2.z; al[mf][2] = U1.w; al[mf][3] = U2.w;
        }
#pragma unroll
        for (int g = 0; g < 8; g++) {
            uint4 V = B4[(wn + g * 8 + qr) * TROW + s * 4 + q];
#pragma unroll
            for (int mf = 0; mf < 2; mf++) {
                mma_bf16(acc[mf][g], ah[mf], V.x, V.y);   // hi*hi
                mma_bf16(acc[mf][g], al[mf], V.x, V.y);   // lo*hi
                mma_bf16(acc[mf][g], ah[mf], V.z, V.w);   // hi*lo
            }
        }
    }
}

// ================= GEMM1: h = gelu(x[tok] @ W1 + b1) =================
__global__ __launch_bounds__(256, 2) void ffn1_hmma(const float* __restrict__ x,
                                                    const float* __restrict__ b1) {
    extern __shared__ uint4 sm4[];
    const int e = blockIdx.z;
    const int cnt = g_cnt[e];
    const int mbase = blockIdx.y * 128;
    if (mbase >= cnt) return;
    const int nbase = blockIdx.x * 128;

    const int tid = threadIdx.x, wid = tid >> 5, lid = tid & 31;
    const int wm = (wid & 3) * 32, wn = (wid >> 2) * 64;

    int*   stok  = reinterpret_cast<int*>(sm4);
    float* sbias = reinterpret_cast<float*>(sm4) + 128;

    if (tid < 128) {
        int mi = mbase + tid;
        stok[tid]  = (mi < cnt) ? g_tok[e * NT + mi] : g_tok[e * NT + mbase];
        sbias[tid] = b1[e * FF + nbase + tid];
    }
    __syncthreads();

    // staging: thread -> (row, khalf); both operands k-consecutive in gmem
    const int row = tid >> 1, khalf = tid & 1;
    const float* arow = x + (size_t)stok[row] * DM + khalf * 16;
    const float* brow = g_w1t + (size_t)e * FF * DM + (size_t)(nbase + row) * DM + khalf * 16;
    const int slot = row * TROW + khalf * 4;

    float acc[2][8][4];
#pragma unroll
    for (int i = 0; i < 2; i++)
#pragma unroll
        for (int j = 0; j < 8; j++)
#pragma unroll
            for (int k = 0; k < 4; k++) acc[i][j][k] = 0.f;

    float4 ra[4], rb[4];
#pragma unroll
    for (int j = 0; j < 4; j++) {
        ra[j] = *reinterpret_cast<const float4*>(arow + j * 4);
        rb[j] = *reinterpret_cast<const float4*>(brow + j * 4);
    }

    int buf = 0;
    for (int kt = 0; kt < DM; kt += 32) {
        uint4* As = sm4 + HDR4 + buf * STAGE4;
        uint4* Bs = As + TILE4;
        uint4 pa[4], pb[4];
        pack16(pa, ra);
        pack16(pb, rb);
#pragma unroll
        for (int q = 0; q < 4; q++) { As[slot + q] = pa[q]; Bs[slot + q] = pb[q]; }
        __syncthreads();
        if (kt + 32 < DM) {   // prefetch next stage; overlaps compute
#pragma unroll
            for (int j = 0; j < 4; j++) {
                ra[j] = *reinterpret_cast<const float4*>(arow + kt + 32 + j * 4);
                rb[j] = *reinterpret_cast<const float4*>(brow + kt + 32 + j * 4);
            }
        }
        compute_stage32(sm4 + HDR4 + buf * STAGE4,
                        sm4 + HDR4 + buf * STAGE4 + TILE4, wm, wn, lid, acc);
        buf ^= 1;
    }

    // epilogue: bias + exact GELU -> fp32 h (validated R7/R12)
    const int hoff = g_off[e];
    const int qr = lid >> 2, c2 = (lid & 3) * 2;
#pragma unroll
    for (int mf = 0; mf < 2; mf++)
#pragma unroll
        for (int half = 0; half < 2; half++) {
            int m = mbase + wm + mf * 16 + qr + half * 8;
            if (m < cnt) {
                float* hr = g_h + (size_t)(hoff + m) * FF + nbase;
#pragma unroll
                for (int g = 0; g < 8; g++) {
                    int cl = wn + g * 8 + c2;
                    float v0 = acc[mf][g][half * 2]     + sbias[cl];
                    float v1 = acc[mf][g][half * 2 + 1] + sbias[cl + 1];
                    hr[cl]     = 0.5f * v0 * (1.f + erff(v0 * 0.70710678118654752f));
                    hr[cl + 1] = 0.5f * v1 * (1.f + erff(v1 * 0.70710678118654752f));
                }
            }
        }
}

// ================= GEMM2: out[tok] += w * (h @ W2 + b2) =================
__global__ __launch_bounds__(256, 2) void ffn2_hmma(const float* __restrict__ b2,
                                                    float* __restrict__ out) {
    extern __shared__ uint4 sm4[];
    const int e = blockIdx.z;
    const int cnt = g_cnt[e];
    const int mbase = blockIdx.y * 128;
    if (mbase >= cnt) return;
    const int nbase = blockIdx.x * 128;

    const int tid = threadIdx.x, wid = tid >> 5, lid = tid & 31;
    const int wm = (wid & 3) * 32, wn = (wid >> 2) * 64;

    int*   stok  = reinterpret_cast<int*>(sm4);
    float* sbias = reinterpret_cast<float*>(sm4) + 128;
    float* swt   = reinterpret_cast<float*>(sm4) + 256;

    if (tid < 128) {
        int mi = mbase + tid;
        bool v = mi < cnt;
        stok[tid]  = v ? g_tok[e * NT + mi] : 0;
        swt[tid]   = v ? g_w  [e * NT + mi] : 0.f;
        sbias[tid] = b2[e * DM + nbase + tid];
    }
    __syncthreads();

    const int hoff = g_off[e];
    const int row = tid >> 1, khalf = tid & 1;
    const float* arow = g_h + (size_t)(hoff + mbase + row) * FF + khalf * 16;   // padded
    const float* brow = g_w2t + (size_t)e * DM * FF + (size_t)(nbase + row) * FF + khalf * 16;
    const int slot = row * TROW + khalf * 4;

    float acc[2][8][4];
#pragma unroll
    for (int i = 0; i < 2; i++)
#pragma unroll
        for (int j = 0; j < 8; j++)
#pragma unroll
            for (int k = 0; k < 4; k++) acc[i][j][k] = 0.f;

    float4 ra[4], rb[4];
#pragma unroll
    for (int j = 0; j < 4; j++) {
        ra[j] = *reinterpret_cast<const float4*>(arow + j * 4);
        rb[j] = *reinterpret_cast<const float4*>(brow + j * 4);
    }

    int buf = 0;
    for (int kt = 0; kt < FF; kt += 32) {
        uint4* As = sm4 + HDR4 + buf * STAGE4;
        uint4* Bs = As + TILE4;
        uint4 pa[4], pb[4];
        pack16(pa, ra);
        pack16(pb, rb);
#pragma unroll
        for (int q = 0; q < 4; q++) { As[slot + q] = pa[q]; Bs[slot + q] = pb[q]; }
        __syncthreads();
        if (kt + 32 < FF) {
#pragma unroll
            for (int j = 0; j < 4; j++) {
                ra[j] = *reinterpret_cast<const float4*>(arow + kt + 32 + j * 4);
                rb[j] = *reinterpret_cast<const float4*>(brow + kt + 32 + j * 4);
            }
        }
        compute_stage32(sm4 + HDR4 + buf * STAGE4,
                        sm4 + HDR4 + buf * STAGE4 + TILE4, wm, wn, lid, acc);
        buf ^= 1;
    }

    // epilogue: bias + gate-weighted scatter (validated R7/R12)
    const int qr = lid >> 2, c2 = (lid & 3) * 2;
#pragma unroll
    for (int mf = 0; mf < 2; mf++)
#pragma unroll
        for (int half = 0; half < 2; half++) {
            int mloc = wm + mf * 16 + qr + half * 8;
            int m = mbase + mloc;
            if (m < cnt) {
                int   tok = stok[mloc];
                float wv  = swt[mloc];
                float* orow = out + (size_t)tok * DM + nbase;
#pragma unroll
                for (int g = 0; g < 8; g++) {
                    int cl = wn + g * 8 + c2;
                    atomicAdd(&orow[cl],     wv * (acc[mf][g][half * 2]     + sbias[cl]));
                    atomicAdd(&orow[cl + 1], wv * (acc[mf][g][half * 2 + 1] + sbias[cl + 1]));
                }
            }
        }
}

// ---------------------------------------------------------------
extern "C" void kernel_launch(void* const* d_in, const int* in_sizes, int n_in,
                              void* d_out, int out_size) {
    const float* x  = (const float*)d_in[0];
    const float* Wg = (const float*)d_in[1];
    const float* bg = (const float*)d_in[2];
    const float* W1 = (const float*)d_in[3];
    const float* b1 = (const float*)d_in[4];
    const float* W2 = (const float*)d_in[5];
    const float* b2 = (const float*)d_in[6];
    float* out = (float*)d_out;

    cudaFuncSetAttribute(ffn1_hmma, cudaFuncAttributeMaxDynamicSharedMemorySize, SMEM_BYTES);
    cudaFuncSetAttribute(ffn2_hmma, cudaFuncAttributeMaxDynamicSharedMemorySize, SMEM_BYTES);

    float* w1t; cudaGetSymbolAddress((void**)&w1t, g_w1t);
    float* w2t; cudaGetSymbolAddress((void**)&w2t, g_w2t);

    zero_kernel<<<NT * DM / 4 / 256, 256>>>(out);
    gate_kernel<<<1024, 256>>>(x, Wg, bg);
    offsets_kernel<<<1, 32>>>();
    // W1 [E][DM][FF] -> W1t [E][FF][DM]
    wtrans<<<dim3(FF / 32, DM / 32, NE), 256>>>(W1, w1t, DM, FF);
    // W2 [E][FF][DM] -> W2t [E][DM][FF]
    wtrans<<<dim3(DM / 32, FF / 32, NE), 256>>>(W2, w2t, FF, DM);

    ffn1_hmma<<<dim3(FF / 128, NT / 128, NE), 256, SMEM_BYTES>>>(x, b1);
    ffn2_hmma<<<dim3(DM / 128, NT / 128, NE), 256, SMEM_BYTES>>>(b2, out);
}